// round 1
// baseline (speedup 1.0000x reference)
#include <cuda_runtime.h>
#include <cuda_bf16.h>
#include <cstdint>

#define Hd 512
#define Wd 512
#define HW (512*512)
#define Cc 64
#define Md 64
#define Ll 4

// ---------------- scratch (device globals; no runtime allocation) ----------------
__device__ float  d_v[Cc*HW];          // 64 MB  current features
__device__ float  d_s[Cc*HW];          // 64 MB  spectral conv output
__device__ float2 d_P[Cc*Hd*Md];       // 16 MB  after W-DFT  (re,im)
__device__ float2 d_G[Cc*Hd*Md];       // 16 MB  after inv H-DFT
__device__ float2 d_c[Cc*Md*Md];       // 2 MB   spectrum (centered modes)
__device__ float2 d_dm[Cc*Md*Md];      // 2 MB   mixed spectrum
// DFT tables
__device__ float2 t_wf[Wd*Md];         // [w][n]  (cos, -sin)/ (H*W)
__device__ float2 t_hf[Md*Hd];         // [m][h]  (cos, sin), freq = m-32
__device__ float2 t_wi[Md*Wd];         // [n][w]  alpha_n * (cos, sin)

__device__ __forceinline__ float gelu_f(float x){
    float x3 = x*x*x;
    float t  = tanhf(0.7978845608028654f*(x + 0.044715f*x3));
    return 0.5f*x*(1.0f+t);
}

// ---------------- table init (recomputed each launch; deterministic) -------------
__global__ void k_tables(){
    int idx = blockIdx.x*256 + threadIdx.x;
    if (idx >= Wd*Md) return;
    // t_wf : [w][n]
    {
        int w = idx >> 6, n = idx & 63;
        float s, c;
        sincospif((float)(n*w) * (1.0f/256.0f), &s, &c);
        const float nrm = 1.0f/(float)(HW);
        t_wf[idx] = make_float2(c*nrm, -s*nrm);
    }
    // t_hf : [m][h], frequency m-32
    {
        int m = idx >> 9, h = idx & 511;
        float s, c;
        sincospif((float)((m-32)*h) * (1.0f/256.0f), &s, &c);
        t_hf[idx] = make_float2(c, s);
    }
    // t_wi : [n][w], alpha folded
    {
        int n = idx >> 9, w = idx & 511;
        float s, c;
        sincospif((float)(n*w) * (1.0f/256.0f), &s, &c);
        float a = (n==0) ? 1.0f : 2.0f;
        t_wi[idx] = make_float2(a*c, a*s);
    }
}

// ---------------- encoder: v[c] = ew[c,0]*x0 + ew[c,1]*x1 + ew[c,2]*u + eb[c] ----
__global__ void k_enc(const float* __restrict__ u, const float* __restrict__ x,
                      const float* __restrict__ ew, const float* __restrict__ eb){
    int p  = blockIdx.x*256 + threadIdx.x;
    int ch = blockIdx.y;
    float w0 = ew[ch*3+0], w1 = ew[ch*3+1], w2 = ew[ch*3+2];
    d_v[ch*HW + p] = w0*x[p] + w1*x[HW+p] + w2*u[p] + eb[ch];
}

// ---------------- forward W-DFT: P[ch,h,n] = sum_w v[ch,h,w] * e^{-i 2pi n w/W}/N --
// grid (32 htiles, 64 ch), 64 threads (one per n), 16 h-rows per block
__global__ void k_fwdW(){
    int ch = blockIdx.y, h0 = blockIdx.x*16;
    __shared__ float vs[16*512];
    const float4* vb = (const float4*)(d_v + (size_t)(ch*Hd + h0)*Wd);
    float4* vs4 = (float4*)vs;
    for (int idx = threadIdx.x; idx < 2048; idx += 64) vs4[idx] = vb[idx];
    __syncthreads();
    int n = threadIdx.x;
    float ar[16], ai[16];
#pragma unroll
    for (int r=0;r<16;r++){ ar[r]=0.f; ai[r]=0.f; }
    for (int w4=0; w4<128; w4++){
        float2 t0 = t_wf[(w4*4+0)*64+n];
        float2 t1 = t_wf[(w4*4+1)*64+n];
        float2 t2 = t_wf[(w4*4+2)*64+n];
        float2 t3 = t_wf[(w4*4+3)*64+n];
#pragma unroll
        for (int r=0;r<16;r++){
            float4 v4 = vs4[r*128 + w4];
            ar[r] += v4.x*t0.x + v4.y*t1.x + v4.z*t2.x + v4.w*t3.x;
            ai[r] += v4.x*t0.y + v4.y*t1.y + v4.z*t2.y + v4.w*t3.y;
        }
    }
    float2* Pout = d_P + (size_t)(ch*Hd + h0)*Md + n;
#pragma unroll
    for (int r=0;r<16;r++) Pout[r*Md] = make_float2(ar[r], ai[r]);
}

// ---------------- forward H-DFT: c[ch,m,n] = sum_h e^{-i 2pi (m-32) h/H} P[ch,h,n]
// grid (16 mtiles, 64 ch), 64 threads (n), 4 m per block
__global__ void k_fwdH(){
    int ch = blockIdx.y, m0 = blockIdx.x*4;
    int n  = threadIdx.x;
    const float2* P = d_P + (size_t)ch*Hd*Md + n;
    float cr[4], ci[4];
#pragma unroll
    for (int k=0;k<4;k++){ cr[k]=0.f; ci[k]=0.f; }
    for (int h=0; h<Hd; h++){
        float2 p = P[h*Md];
#pragma unroll
        for (int k=0;k<4;k++){
            float2 t = t_hf[(m0+k)*Hd + h];      // (cos, sin); kernel uses e^{-i}
            cr[k] += t.x*p.x + t.y*p.y;
            ci[k] += t.x*p.y - t.y*p.x;
        }
    }
#pragma unroll
    for (int k=0;k<4;k++)
        d_c[(size_t)(ch*Md + m0 + k)*Md + n] = make_float2(cr[k], ci[k]);
}

// ---------------- per-mode channel mixing: d[o,mode] = sum_i A[o,i,mode]*c[i,mode]
// grid (16, 64 o), 256 threads; HBM-bound on A
__global__ void k_mix(const float* __restrict__ Ar, const float* __restrict__ Ai){
    int o    = blockIdx.y;
    int mode = blockIdx.x*256 + threadIdx.x;     // 0..4095
    const float* arp = Ar + (size_t)o*Cc*4096 + mode;
    const float* aip = Ai + (size_t)o*Cc*4096 + mode;
    float dr = 0.f, di = 0.f;
#pragma unroll 4
    for (int i=0; i<Cc; i++){
        float a = __ldg(arp + (size_t)i*4096);
        float b = __ldg(aip + (size_t)i*4096);
        float2 c = d_c[(size_t)i*4096 + mode];
        dr += a*c.x - b*c.y;
        di += a*c.y + b*c.x;
    }
    d_dm[(size_t)o*4096 + mode] = make_float2(dr, di);
}

// ---------------- inverse H-DFT: G[ch,h,n] = sum_m e^{+i 2pi (m-32) h/H} d[ch,m,n]
// grid (128 htiles, 64 ch), 64 threads (n), 4 h per block
__global__ void k_invH(){
    int ch = blockIdx.y, h0 = blockIdx.x*4;
    int n  = threadIdx.x;
    const float2* D = d_dm + (size_t)ch*4096 + n;
    float gr[4], gi[4];
#pragma unroll
    for (int r=0;r<4;r++){ gr[r]=0.f; gi[r]=0.f; }
    for (int m=0; m<Md; m++){
        float2 dd = D[m*Md];
#pragma unroll
        for (int r=0;r<4;r++){
            float2 t = t_hf[m*Hd + h0 + r];      // e^{+i}
            gr[r] += t.x*dd.x - t.y*dd.y;
            gi[r] += t.x*dd.y + t.y*dd.x;
        }
    }
#pragma unroll
    for (int r=0;r<4;r++)
        d_G[(size_t)(ch*Hd + h0 + r)*Md + n] = make_float2(gr[r], gi[r]);
}

// ---------------- inverse W-DFT: s[ch,h,w] = Re sum_n alpha_n G[ch,h,n] e^{+i 2pi n w/W}
// grid (32 htiles, 64 ch), 128 threads (w, w+128, w+256, w+384), 16 h per block
__global__ void __launch_bounds__(128) k_invW(){
    int ch = blockIdx.y, h0 = blockIdx.x*16;
    __shared__ float2 gs[16*64];
    const float2* G = d_G + (size_t)(ch*Hd + h0)*Md;
    for (int idx = threadIdx.x; idx < 1024; idx += 128) gs[idx] = G[idx];
    __syncthreads();
    int w = threadIdx.x;
    float a0[16], a1[16], a2[16], a3[16];
#pragma unroll
    for (int r=0;r<16;r++){ a0[r]=0.f; a1[r]=0.f; a2[r]=0.f; a3[r]=0.f; }
    for (int n=0; n<Md; n++){
        float2 t0 = t_wi[n*Wd + w];
        float2 t1 = t_wi[n*Wd + w + 128];
        float2 t2 = t_wi[n*Wd + w + 256];
        float2 t3 = t_wi[n*Wd + w + 384];
#pragma unroll
        for (int r=0;r<16;r++){
            float2 g = gs[r*64 + n];
            a0[r] += g.x*t0.x - g.y*t0.y;
            a1[r] += g.x*t1.x - g.y*t1.y;
            a2[r] += g.x*t2.x - g.y*t2.y;
            a3[r] += g.x*t3.x - g.y*t3.y;
        }
    }
#pragma unroll
    for (int r=0;r<16;r++){
        size_t base = (size_t)(ch*Hd + h0 + r)*Wd + w;
        d_s[base      ] = a0[r];
        d_s[base + 128] = a1[r];
        d_s[base + 256] = a2[r];
        d_s[base + 384] = a3[r];
    }
}

// ---------------- fused residual block: v += gelu(W2 gelu(W1 s + b1) + b2) -------
// grid 4096 (64-pixel tiles), 256 threads = (64 px) x (4 groups of 16 channels)
__global__ void k_resid(const float* __restrict__ W1, const float* __restrict__ b1,
                        const float* __restrict__ W2, const float* __restrict__ b2){
    __shared__ float s_s[64*64];     // [i][px] then reused as g1 [j][px]
    __shared__ float w_t[64*68];     // transposed weights, padded rows
    int tid = threadIdx.x;
    int px  = tid & 63, grp = tid >> 6;     // grp 0..3
    int pbase = blockIdx.x*64;

    // stage s tile + W1^T
    for (int idx = tid; idx < 4096; idx += 256){
        int a = idx >> 6, b = idx & 63;
        s_s[a*64 + b] = d_s[(size_t)a*HW + pbase + b];   // a=i, b=px
        w_t[b*68 + a] = W1[a*64 + b];                    // a=j, b=i -> w_t[i][j]
    }
    __syncthreads();

    int j0 = grp*16;
    float acc[16];
#pragma unroll
    for (int jj=0;jj<16;jj++) acc[jj] = __ldg(b1 + j0 + jj);
    for (int i=0;i<64;i++){
        float sv = s_s[i*64 + px];
        const float4* wp = (const float4*)&w_t[i*68 + j0];
        float4 w0 = wp[0], w1v = wp[1], w2v = wp[2], w3v = wp[3];
        acc[0] += w0.x*sv;  acc[1] += w0.y*sv;  acc[2] += w0.z*sv;  acc[3] += w0.w*sv;
        acc[4] += w1v.x*sv; acc[5] += w1v.y*sv; acc[6] += w1v.z*sv; acc[7] += w1v.w*sv;
        acc[8] += w2v.x*sv; acc[9] += w2v.y*sv; acc[10]+= w2v.z*sv; acc[11]+= w2v.w*sv;
        acc[12]+= w3v.x*sv; acc[13]+= w3v.y*sv; acc[14]+= w3v.z*sv; acc[15]+= w3v.w*sv;
    }
#pragma unroll
    for (int jj=0;jj<16;jj++) acc[jj] = gelu_f(acc[jj]);
    __syncthreads();
    // write g1 over s_s; stage W2^T (w_t[j][ch])
#pragma unroll
    for (int jj=0;jj<16;jj++) s_s[(j0+jj)*64 + px] = acc[jj];
    for (int idx = tid; idx < 4096; idx += 256){
        int chh = idx >> 6, j = idx & 63;
        w_t[j*68 + chh] = W2[chh*64 + j];
    }
    __syncthreads();

    int c0 = grp*16;
    float acc2[16];
#pragma unroll
    for (int cc=0;cc<16;cc++) acc2[cc] = 0.f;
    for (int j=0;j<64;j++){
        float gv = s_s[j*64 + px];
        const float4* wp = (const float4*)&w_t[j*68 + c0];
        float4 w0 = wp[0], w1v = wp[1], w2v = wp[2], w3v = wp[3];
        acc2[0] += w0.x*gv;  acc2[1] += w0.y*gv;  acc2[2] += w0.z*gv;  acc2[3] += w0.w*gv;
        acc2[4] += w1v.x*gv; acc2[5] += w1v.y*gv; acc2[6] += w1v.z*gv; acc2[7] += w1v.w*gv;
        acc2[8] += w2v.x*gv; acc2[9] += w2v.y*gv; acc2[10]+= w2v.z*gv; acc2[11]+= w2v.w*gv;
        acc2[12]+= w3v.x*gv; acc2[13]+= w3v.y*gv; acc2[14]+= w3v.z*gv; acc2[15]+= w3v.w*gv;
    }
#pragma unroll
    for (int cc=0;cc<16;cc++){
        int ch = c0 + cc;
        size_t idx = (size_t)ch*HW + pbase + px;
        d_v[idx] = d_v[idx] + gelu_f(acc2[cc] + __ldg(b2 + ch));
    }
}

// ---------------- decoder -------------------------------------------------------
__global__ void k_dec(const float* __restrict__ dw, const float* __restrict__ db,
                      float* __restrict__ out){
    int p = blockIdx.x*256 + threadIdx.x;
    float acc = db[0];
#pragma unroll 8
    for (int i=0;i<Cc;i++) acc += dw[i] * d_v[(size_t)i*HW + p];
    out[p] = acc;
}

// ---------------- launch --------------------------------------------------------
extern "C" void kernel_launch(void* const* d_in, const int* in_sizes, int n_in,
                              void* d_out, int out_size){
    const float* u    = (const float*)d_in[0];
    const float* x    = (const float*)d_in[1];
    const float* encw = (const float*)d_in[2];
    const float* encb = (const float*)d_in[3];
    const float* decw = (const float*)d_in[4];
    const float* decb = (const float*)d_in[5];
    const float* c1w  = (const float*)d_in[6];
    const float* c1b  = (const float*)d_in[7];
    const float* c2w  = (const float*)d_in[8];
    const float* c2b  = (const float*)d_in[9];
    const float* Are  = (const float*)d_in[10];
    const float* Aim  = (const float*)d_in[11];
    float* out = (float*)d_out;

    k_tables<<<128, 256>>>();
    k_enc<<<dim3(HW/256, Cc), 256>>>(u, x, encw, encb);

    for (int l=0; l<Ll; l++){
        k_fwdW<<<dim3(32, Cc), 64>>>();
        k_fwdH<<<dim3(16, Cc), 64>>>();
        k_mix<<<dim3(16, Cc), 256>>>(Are + (size_t)l*Cc*Cc*4096,
                                     Aim + (size_t)l*Cc*Cc*4096);
        k_invH<<<dim3(128, Cc), 64>>>();
        k_invW<<<dim3(32, Cc), 128>>>();
        k_resid<<<HW/64, 256>>>(c1w + l*4096, c1b + l*64,
                                c2w + l*4096, c2b + l*64);
    }

    k_dec<<<HW/256, 256>>>(decw, decb, out);
}